// round 12
// baseline (speedup 1.0000x reference)
#include <cuda_runtime.h>
#include <cuda_fp16.h>
#include <cstdint>

#define HID 4096
#define BATCH 8192
#define NEXC 3276   // int(0.8 * 4096): columns < NEXC are excitatory

// Scratch: fp16 operands (16B-aligned for cp.async).
__device__ __align__(128) __half g_WH[(size_t)HID * HID];
__device__ __align__(128) __half g_XH[(size_t)BATCH * HID];

// ---------------------------------------------------------------------------
// Prep: mask + Dale clip -> fp16 W (dale sign from column index); x -> fp16
// ---------------------------------------------------------------------------

__global__ void prep_w_kernel(const float* __restrict__ w,
                              const int* __restrict__ sp) {
    size_t i = ((size_t)blockIdx.x * blockDim.x + threadIdx.x) * 4;
    float4 wv = *reinterpret_cast<const float4*>(w + i);
    int4 sv = *reinterpret_cast<const int4*>(sp + i);
    float r[4] = {wv.x, wv.y, wv.z, wv.w};
    int ss[4] = {sv.x, sv.y, sv.z, sv.w};
    int col0 = (int)(i & (HID - 1));
    __half h[4];
#pragma unroll
    for (int j = 0; j < 4; j++) {
        float v = ss[j] ? r[j] : 0.0f;
        v = (col0 + j < NEXC) ? fmaxf(v, 0.0f) : fminf(v, 0.0f);
        h[j] = __float2half_rn(v);
    }
    __half2* ph = reinterpret_cast<__half2*>(&g_WH[i]);
    ph[0] = __halves2half2(h[0], h[1]);
    ph[1] = __halves2half2(h[2], h[3]);
}

__global__ void prep_x_kernel(const float* __restrict__ x) {
    size_t i = ((size_t)blockIdx.x * blockDim.x + threadIdx.x) * 4;
    float4 xv = *reinterpret_cast<const float4*>(x + i);
    __half2* ph = reinterpret_cast<__half2*>(&g_XH[i]);
    ph[0] = __halves2half2(__float2half_rn(xv.x), __float2half_rn(xv.y));
    ph[1] = __halves2half2(__float2half_rn(xv.z), __float2half_rn(xv.w));
}

// ---------------------------------------------------------------------------
// Pipelined mma.sync GEMM: out = X @ W^T + bias, fp16 x fp16 -> fp32 accum.
// CTA 128x256, 8 warps (2Mx4N), warp tile 64x64, BK=32, 8-stage cp.async,
// 1 CTA/SM.
// ---------------------------------------------------------------------------

#define BM 128
#define BN 256
#define BK 32
#define NKT (HID / BK)              // 128
#define NSTAGE 8
#define A_PANEL (BM * 64)           // 8 KB  (128 rows x 32 fp16)
#define B_PANEL (BN * 64)           // 16 KB (256 rows x 32 fp16)
#define STAGE_BYTES (A_PANEL + B_PANEL)     // 24 KB
#define SMEM_BYTES (NSTAGE * STAGE_BYTES)   // 192 KB (epilogue reuses)

__device__ __forceinline__ uint32_t smem_u32(const void* p) {
    uint32_t a;
    asm("{ .reg .u64 t; cvta.to.shared.u64 t, %1; cvt.u32.u64 %0, t; }" : "=r"(a) : "l"(p));
    return a;
}

// swizzled byte offset inside a panel: row, ck = 16B chunk (0..3)
__device__ __forceinline__ uint32_t swz(uint32_t row, uint32_t ck) {
    return row * 64u + ((ck ^ ((row >> 1) & 3u)) << 4);
}

__device__ __forceinline__ void cpasync16(uint32_t saddr, const void* gptr) {
    asm volatile("cp.async.cg.shared.global [%0], [%1], 16;" :: "r"(saddr), "l"(gptr));
}

#define LDSM4(r, addr) \
    asm volatile("ldmatrix.sync.aligned.m8n8.x4.shared.b16 {%0,%1,%2,%3}, [%4];" \
                 : "=r"((r)[0]), "=r"((r)[1]), "=r"((r)[2]), "=r"((r)[3]) : "r"(addr))

#define MMA16816(d, a, b0, b1) \
    asm volatile("mma.sync.aligned.m16n8k16.row.col.f32.f16.f16.f32 " \
                 "{%0,%1,%2,%3}, {%4,%5,%6,%7}, {%8,%9}, {%0,%1,%2,%3};" \
                 : "+f"((d)[0]), "+f"((d)[1]), "+f"((d)[2]), "+f"((d)[3]) \
                 : "r"((a)[0]), "r"((a)[1]), "r"((a)[2]), "r"((a)[3]), \
                   "r"(b0), "r"(b1))

__global__ __launch_bounds__(256, 1)
void gemm_kernel(float* __restrict__ out, const float* __restrict__ bias) {
    extern __shared__ char smem[];
    const uint32_t sb = smem_u32(smem);
    const int tid = threadIdx.x;
    const int warp = tid >> 5;
    const int lane = tid & 31;

    const int ntn = HID / BN;                 // 16, N fastest -> X reuse in L2
    const int m0 = (blockIdx.x / ntn) * BM;
    const int n0 = (blockIdx.x % ntn) * BN;

    const int wm = (warp & 1) * 64;           // warp M offset
    const int wn = (warp >> 1) * 64;          // warp N offset

    float acc[4][8][4];
#pragma unroll
    for (int mi = 0; mi < 4; mi++)
#pragma unroll
        for (int ni = 0; ni < 8; ni++)
#pragma unroll
            for (int e = 0; e < 4; e++) acc[mi][ni][e] = 0.0f;

    // ---- global -> shared: 6 x 16B cp.async per thread per k-tile ----
    auto issue = [&](int kt) {
        const uint32_t st = sb + (uint32_t)(kt & (NSTAGE - 1)) * STAGE_BYTES;
        const int k0 = kt * BK;
#pragma unroll
        for (int i = 0; i < 6; i++) {
            int id = i * 256 + tid;            // 0..1535
            if (id < 512) {                    // A panel: 128 rows x 4 chunks
                int r = id >> 2, c = id & 3;
                cpasync16(st + swz((uint32_t)r, (uint32_t)c),
                          g_XH + (size_t)(m0 + r) * HID + k0 + c * 8);
            } else {                           // B panel: 256 rows x 4 chunks
                int idb = id - 512;
                int r = idb >> 2, c = idb & 3;
                cpasync16(st + A_PANEL + swz((uint32_t)r, (uint32_t)c),
                          g_WH + (size_t)(n0 + r) * HID + k0 + c * 8);
            }
        }
    };

    // prologue: 7 stages in flight
#pragma unroll
    for (int s = 0; s < NSTAGE - 1; s++) {
        issue(s);
        asm volatile("cp.async.commit_group;" ::: "memory");
    }

    // per-lane ldmatrix source coordinates
    const int arow = lane & 15;               // A: lanes 0-15 rows, 16-31 k+8
    const int ack = lane >> 4;
    const int brow = (lane & 7) + ((lane >> 4) << 3);  // B: 2 n8-tiles per x4
    const int bck = (lane >> 3) & 1;

    for (int kt = 0; kt < NKT; kt++) {
        asm volatile("cp.async.wait_group 6;" ::: "memory");
        __syncthreads();

        const uint32_t st = sb + (uint32_t)(kt & (NSTAGE - 1)) * STAGE_BYTES;
        const uint32_t aH = st;
        const uint32_t bH = st + A_PANEL;

#pragma unroll
        for (int kh = 0; kh < 2; kh++) {
            uint32_t ra[4][4], rb[4][4];
#pragma unroll
            for (int mi = 0; mi < 4; mi++)
                LDSM4(ra[mi], aH + swz((uint32_t)(wm + mi * 16 + arow),
                                       (uint32_t)(kh * 2 + ack)));
#pragma unroll
            for (int nj = 0; nj < 4; nj++)
                LDSM4(rb[nj], bH + swz((uint32_t)(wn + nj * 16 + brow),
                                       (uint32_t)(kh * 2 + bck)));
#pragma unroll
            for (int mi = 0; mi < 4; mi++)
#pragma unroll
                for (int ni = 0; ni < 8; ni++)
                    MMA16816(acc[mi][ni], ra[mi],
                             rb[ni >> 1][(ni & 1) * 2], rb[ni >> 1][(ni & 1) * 2 + 1]);
        }

        if (kt + NSTAGE - 1 < NKT) issue(kt + NSTAGE - 1);
        asm volatile("cp.async.commit_group;" ::: "memory");
    }

    // ---- epilogue: regs -> smem (stride 264) -> coalesced STG + bias ----
    __syncthreads();
    float* C = reinterpret_cast<float*>(smem);
    const int g = lane >> 2, tg = lane & 3;
#pragma unroll
    for (int mi = 0; mi < 4; mi++) {
#pragma unroll
        for (int ni = 0; ni < 8; ni++) {
            int row = wm + mi * 16 + g;
            int col = wn + ni * 8 + tg * 2;
            *reinterpret_cast<float2*>(&C[row * 264 + col]) =
                make_float2(acc[mi][ni][0], acc[mi][ni][1]);
            *reinterpret_cast<float2*>(&C[(row + 8) * 264 + col]) =
                make_float2(acc[mi][ni][2], acc[mi][ni][3]);
        }
    }
    __syncthreads();
#pragma unroll
    for (int i = 0; i < 32; i++) {
        int idx = tid + i * 256;
        int row = idx >> 6;                    // 64 float4 per row of 256 cols
        int col = (idx & 63) * 4;
        float4 b = *reinterpret_cast<const float4*>(bias + n0 + col);
        float4 v = *reinterpret_cast<const float4*>(&C[row * 264 + col]);
        v.x += b.x; v.y += b.y; v.z += b.z; v.w += b.w;
        *reinterpret_cast<float4*>(out + (size_t)(m0 + row) * HID + n0 + col) = v;
    }
}

// ---------------------------------------------------------------------------

extern "C" void kernel_launch(void* const* d_in, const int* in_sizes, int n_in,
                              void* d_out, int out_size) {
    const float* x    = (const float*)d_in[0];
    const float* w    = (const float*)d_in[1];
    const float* bias = (const float*)d_in[2];
    const int* sp     = (const int*)d_in[4];
    float* out = (float*)d_out;
    (void)in_sizes; (void)n_in; (void)out_size;

    cudaFuncSetAttribute(gemm_kernel, cudaFuncAttributeMaxDynamicSharedMemorySize,
                         SMEM_BYTES);

    prep_w_kernel<<<(size_t)HID * HID / 4 / 256, 256>>>(w, sp);
    prep_x_kernel<<<(size_t)BATCH * HID / 4 / 256, 256>>>(x);
    gemm_kernel<<<(BATCH / BM) * (HID / BN), 256, SMEM_BYTES>>>(out, bias);
}

// round 13
// speedup vs baseline: 1.1670x; 1.1670x over previous
#include <cuda_runtime.h>
#include <cuda_fp16.h>
#include <cstdint>

#define HID 4096
#define BATCH 8192
#define NEXC 3276   // int(0.8 * 4096): columns < NEXC are excitatory

// Scratch: fp16 operands (16B-aligned for cp.async).
__device__ __align__(128) __half g_WH[(size_t)HID * HID];
__device__ __align__(128) __half g_XH[(size_t)BATCH * HID];

// ---------------------------------------------------------------------------
// Prep: mask + Dale clip -> fp16 W (dale sign from column index); x -> fp16
// ---------------------------------------------------------------------------

__global__ void prep_w_kernel(const float* __restrict__ w,
                              const int* __restrict__ sp) {
    size_t i = ((size_t)blockIdx.x * blockDim.x + threadIdx.x) * 4;
    float4 wv = *reinterpret_cast<const float4*>(w + i);
    int4 sv = *reinterpret_cast<const int4*>(sp + i);
    float r[4] = {wv.x, wv.y, wv.z, wv.w};
    int ss[4] = {sv.x, sv.y, sv.z, sv.w};
    int col0 = (int)(i & (HID - 1));
    __half h[4];
#pragma unroll
    for (int j = 0; j < 4; j++) {
        float v = ss[j] ? r[j] : 0.0f;
        v = (col0 + j < NEXC) ? fmaxf(v, 0.0f) : fminf(v, 0.0f);
        h[j] = __float2half_rn(v);
    }
    __half2* ph = reinterpret_cast<__half2*>(&g_WH[i]);
    ph[0] = __halves2half2(h[0], h[1]);
    ph[1] = __halves2half2(h[2], h[3]);
}

__global__ void prep_x_kernel(const float* __restrict__ x) {
    size_t i = ((size_t)blockIdx.x * blockDim.x + threadIdx.x) * 4;
    float4 xv = *reinterpret_cast<const float4*>(x + i);
    __half2* ph = reinterpret_cast<__half2*>(&g_XH[i]);
    ph[0] = __halves2half2(__float2half_rn(xv.x), __float2half_rn(xv.y));
    ph[1] = __halves2half2(__float2half_rn(xv.z), __float2half_rn(xv.w));
}

// ---------------------------------------------------------------------------
// Pipelined mma.sync GEMM: out = X @ W^T + bias, fp16 x fp16 -> fp32 accum.
// CTA 128x128 with FOUR warps (2Mx2N), warp tile 64x64, BK=32,
// 6-stage cp.async, 2 CTAs/SM.
// ---------------------------------------------------------------------------

#define BM 128
#define BN 128
#define BK 32
#define NKT (HID / BK)              // 128
#define NSTAGE 6
#define A_PANEL (BM * 64)           // 8 KB (128 rows x 32 fp16)
#define B_PANEL (BN * 64)           // 8 KB
#define STAGE_BYTES (A_PANEL + B_PANEL)     // 16 KB
#define SMEM_BYTES (NSTAGE * STAGE_BYTES)   // 96 KB (epilogue reuses)
#define NTHREADS 128

__device__ __forceinline__ uint32_t smem_u32(const void* p) {
    uint32_t a;
    asm("{ .reg .u64 t; cvta.to.shared.u64 t, %1; cvt.u32.u64 %0, t; }" : "=r"(a) : "l"(p));
    return a;
}

// swizzled byte offset inside a panel: row (0..127), ck = 16B chunk (0..3)
__device__ __forceinline__ uint32_t swz(uint32_t row, uint32_t ck) {
    return row * 64u + ((ck ^ ((row >> 1) & 3u)) << 4);
}

__device__ __forceinline__ void cpasync16(uint32_t saddr, const void* gptr) {
    asm volatile("cp.async.cg.shared.global [%0], [%1], 16;" :: "r"(saddr), "l"(gptr));
}

#define LDSM4(r, addr) \
    asm volatile("ldmatrix.sync.aligned.m8n8.x4.shared.b16 {%0,%1,%2,%3}, [%4];" \
                 : "=r"((r)[0]), "=r"((r)[1]), "=r"((r)[2]), "=r"((r)[3]) : "r"(addr))

#define MMA16816(d, a, b0, b1) \
    asm volatile("mma.sync.aligned.m16n8k16.row.col.f32.f16.f16.f32 " \
                 "{%0,%1,%2,%3}, {%4,%5,%6,%7}, {%8,%9}, {%0,%1,%2,%3};" \
                 : "+f"((d)[0]), "+f"((d)[1]), "+f"((d)[2]), "+f"((d)[3]) \
                 : "r"((a)[0]), "r"((a)[1]), "r"((a)[2]), "r"((a)[3]), \
                   "r"(b0), "r"(b1))

__global__ __launch_bounds__(NTHREADS, 2)
void gemm_kernel(float* __restrict__ out, const float* __restrict__ bias) {
    extern __shared__ char smem[];
    const uint32_t sb = smem_u32(smem);
    const int tid = threadIdx.x;
    const int warp = tid >> 5;
    const int lane = tid & 31;

    const int ntn = HID / BN;                 // 32, N fastest -> X reuse in L2
    const int m0 = (blockIdx.x / ntn) * BM;
    const int n0 = (blockIdx.x % ntn) * BN;

    const int wm = (warp & 1) * 64;           // warp M offset
    const int wn = (warp >> 1) * 64;          // warp N offset

    float acc[4][8][4];
#pragma unroll
    for (int mi = 0; mi < 4; mi++)
#pragma unroll
        for (int ni = 0; ni < 8; ni++)
#pragma unroll
            for (int e = 0; e < 4; e++) acc[mi][ni][e] = 0.0f;

    // ---- global -> shared: 8 x 16B cp.async per thread per k-tile ----
    auto issue = [&](int kt) {
        const uint32_t st = sb + (uint32_t)(kt % NSTAGE) * STAGE_BYTES;
        const int k0 = kt * BK;
#pragma unroll
        for (int i = 0; i < 8; i++) {
            int id = i * NTHREADS + tid;       // 0..1023
            int p = id >> 9;                   // 0 = A panel, 1 = B panel
            int r = (id >> 2) & 127;
            int c = id & 3;
            const __half* src = (p == 0)
                ? g_XH + (size_t)(m0 + r) * HID + k0 + c * 8
                : g_WH + (size_t)(n0 + r) * HID + k0 + c * 8;
            cpasync16(st + (uint32_t)p * A_PANEL + swz((uint32_t)r, (uint32_t)c), src);
        }
    };

    // prologue: 5 stages in flight
#pragma unroll
    for (int s = 0; s < NSTAGE - 1; s++) {
        issue(s);
        asm volatile("cp.async.commit_group;" ::: "memory");
    }

    // per-lane ldmatrix source coordinates
    const int arow = lane & 15;               // A: lanes 0-15 rows, 16-31 k+8
    const int ack = lane >> 4;
    const int brow = (lane & 7) + ((lane >> 4) << 3);  // B: 2 n8-tiles per x4
    const int bck = (lane >> 3) & 1;

    for (int kt = 0; kt < NKT; kt++) {
        asm volatile("cp.async.wait_group 4;" ::: "memory");
        __syncthreads();

        const uint32_t st = sb + (uint32_t)(kt % NSTAGE) * STAGE_BYTES;
        const uint32_t aH = st;
        const uint32_t bH = st + A_PANEL;

#pragma unroll
        for (int kh = 0; kh < 2; kh++) {
            uint32_t ra[4][4], rb[4][4];
#pragma unroll
            for (int mi = 0; mi < 4; mi++)
                LDSM4(ra[mi], aH + swz((uint32_t)(wm + mi * 16 + arow),
                                       (uint32_t)(kh * 2 + ack)));
#pragma unroll
            for (int nj = 0; nj < 4; nj++)
                LDSM4(rb[nj], bH + swz((uint32_t)(wn + nj * 16 + brow),
                                       (uint32_t)(kh * 2 + bck)));
#pragma unroll
            for (int mi = 0; mi < 4; mi++)
#pragma unroll
                for (int ni = 0; ni < 8; ni++)
                    MMA16816(acc[mi][ni], ra[mi],
                             rb[ni >> 1][(ni & 1) * 2], rb[ni >> 1][(ni & 1) * 2 + 1]);
        }

        if (kt + NSTAGE - 1 < NKT) issue(kt + NSTAGE - 1);
        asm volatile("cp.async.commit_group;" ::: "memory");
    }

    // ---- epilogue: regs -> smem (stride 132) -> coalesced STG + bias ----
    __syncthreads();
    float* C = reinterpret_cast<float*>(smem);
    const int g = lane >> 2, tg = lane & 3;
#pragma unroll
    for (int mi = 0; mi < 4; mi++) {
#pragma unroll
        for (int ni = 0; ni < 8; ni++) {
            int row = wm + mi * 16 + g;
            int col = wn + ni * 8 + tg * 2;
            *reinterpret_cast<float2*>(&C[row * 132 + col]) =
                make_float2(acc[mi][ni][0], acc[mi][ni][1]);
            *reinterpret_cast<float2*>(&C[(row + 8) * 132 + col]) =
                make_float2(acc[mi][ni][2], acc[mi][ni][3]);
        }
    }
    __syncthreads();
#pragma unroll
    for (int i = 0; i < 32; i++) {
        int idx = tid + i * NTHREADS;          // 4096 float4 total
        int row = idx >> 5;                    // 32 float4 per row of 128 cols
        int col = (idx & 31) * 4;
        float4 b = *reinterpret_cast<const float4*>(bias + n0 + col);
        float4 v = *reinterpret_cast<const float4*>(&C[row * 132 + col]);
        v.x += b.x; v.y += b.y; v.z += b.z; v.w += b.w;
        *reinterpret_cast<float4*>(out + (size_t)(m0 + row) * HID + n0 + col) = v;
    }
}

// ---------------------------------------------------------------------------

extern "C" void kernel_launch(void* const* d_in, const int* in_sizes, int n_in,
                              void* d_out, int out_size) {
    const float* x    = (const float*)d_in[0];
    const float* w    = (const float*)d_in[1];
    const float* bias = (const float*)d_in[2];
    const int* sp     = (const int*)d_in[4];
    float* out = (float*)d_out;
    (void)in_sizes; (void)n_in; (void)out_size;

    cudaFuncSetAttribute(gemm_kernel, cudaFuncAttributeMaxDynamicSharedMemorySize,
                         SMEM_BYTES);

    prep_w_kernel<<<(size_t)HID * HID / 4 / 256, 256>>>(w, sp);
    prep_x_kernel<<<(size_t)BATCH * HID / 4 / 256, 256>>>(x);
    gemm_kernel<<<(BATCH / BM) * (HID / BN), NTHREADS, SMEM_BYTES>>>(out, bias);
}

// round 14
// speedup vs baseline: 1.2340x; 1.0574x over previous
#include <cuda_runtime.h>
#include <cuda_fp16.h>
#include <cstdint>

#define HID 4096
#define BATCH 8192
#define NEXC 3276   // int(0.8 * 4096): columns < NEXC are excitatory

// Scratch: fp16 operands (16B-aligned for cp.async).
__device__ __align__(128) __half g_WH[(size_t)HID * HID];
__device__ __align__(128) __half g_XH[(size_t)BATCH * HID];

// ---------------------------------------------------------------------------
// Fused prep: blocks [0, WBLK) handle W (mask + Dale clip -> fp16),
//             blocks [WBLK, ...) handle X (fp32 -> fp16).
// ---------------------------------------------------------------------------

#define WBLK ((int)((size_t)HID * HID / 4 / 256))        // 16384
#define XBLK ((int)((size_t)BATCH * HID / 4 / 256))      // 32768

__global__ void prep_kernel(const float* __restrict__ w,
                            const int* __restrict__ sp,
                            const float* __restrict__ x) {
    int b = blockIdx.x;
    if (b < WBLK) {
        size_t i = ((size_t)b * blockDim.x + threadIdx.x) * 4;
        float4 wv = *reinterpret_cast<const float4*>(w + i);
        int4 sv = *reinterpret_cast<const int4*>(sp + i);
        float r[4] = {wv.x, wv.y, wv.z, wv.w};
        int ss[4] = {sv.x, sv.y, sv.z, sv.w};
        int col0 = (int)(i & (HID - 1));
        __half h[4];
#pragma unroll
        for (int j = 0; j < 4; j++) {
            float v = ss[j] ? r[j] : 0.0f;
            v = (col0 + j < NEXC) ? fmaxf(v, 0.0f) : fminf(v, 0.0f);
            h[j] = __float2half_rn(v);
        }
        __half2* ph = reinterpret_cast<__half2*>(&g_WH[i]);
        ph[0] = __halves2half2(h[0], h[1]);
        ph[1] = __halves2half2(h[2], h[3]);
    } else {
        size_t i = ((size_t)(b - WBLK) * blockDim.x + threadIdx.x) * 4;
        float4 xv = *reinterpret_cast<const float4*>(x + i);
        __half2* ph = reinterpret_cast<__half2*>(&g_XH[i]);
        ph[0] = __halves2half2(__float2half_rn(xv.x), __float2half_rn(xv.y));
        ph[1] = __halves2half2(__float2half_rn(xv.z), __float2half_rn(xv.w));
    }
}

// ---------------------------------------------------------------------------
// Pipelined mma.sync GEMM: out = X @ W^T + bias, fp16 x fp16 -> fp32 accum.
// CTA 128x128, FOUR warps (2Mx2N), warp tile 64x64, BK=64,
// 3-stage cp.async, 2 CTAs/SM.
// ---------------------------------------------------------------------------

#define BM 128
#define BN 128
#define BK 64
#define NKT (HID / BK)              // 64
#define NSTAGE 3
#define A_PANEL (BM * 128)          // 16 KB (128 rows x 64 fp16)
#define B_PANEL (BN * 128)          // 16 KB
#define STAGE_BYTES (A_PANEL + B_PANEL)     // 32 KB
#define SMEM_BYTES (NSTAGE * STAGE_BYTES)   // 96 KB (epilogue reuses)
#define NTHREADS 128

__device__ __forceinline__ uint32_t smem_u32(const void* p) {
    uint32_t a;
    asm("{ .reg .u64 t; cvta.to.shared.u64 t, %1; cvt.u32.u64 %0, t; }" : "=r"(a) : "l"(p));
    return a;
}

// swizzled byte offset inside a panel: row (0..127), ck = 16B chunk (0..7)
// 128B rows: XOR chunk with row&7 -> conflict-free ldmatrix and cp.async.
__device__ __forceinline__ uint32_t swz(uint32_t row, uint32_t ck) {
    return row * 128u + ((ck ^ (row & 7u)) << 4);
}

__device__ __forceinline__ void cpasync16(uint32_t saddr, const void* gptr) {
    asm volatile("cp.async.cg.shared.global [%0], [%1], 16;" :: "r"(saddr), "l"(gptr));
}

#define LDSM4(r, addr) \
    asm volatile("ldmatrix.sync.aligned.m8n8.x4.shared.b16 {%0,%1,%2,%3}, [%4];" \
                 : "=r"((r)[0]), "=r"((r)[1]), "=r"((r)[2]), "=r"((r)[3]) : "r"(addr))

#define MMA16816(d, a, b0, b1) \
    asm volatile("mma.sync.aligned.m16n8k16.row.col.f32.f16.f16.f32 " \
                 "{%0,%1,%2,%3}, {%4,%5,%6,%7}, {%8,%9}, {%0,%1,%2,%3};" \
                 : "+f"((d)[0]), "+f"((d)[1]), "+f"((d)[2]), "+f"((d)[3]) \
                 : "r"((a)[0]), "r"((a)[1]), "r"((a)[2]), "r"((a)[3]), \
                   "r"(b0), "r"(b1))

__global__ __launch_bounds__(NTHREADS, 2)
void gemm_kernel(float* __restrict__ out, const float* __restrict__ bias) {
    extern __shared__ char smem[];
    const uint32_t sb = smem_u32(smem);
    const int tid = threadIdx.x;
    const int warp = tid >> 5;
    const int lane = tid & 31;

    const int ntn = HID / BN;                 // 32, N fastest -> X reuse in L2
    const int m0 = (blockIdx.x / ntn) * BM;
    const int n0 = (blockIdx.x % ntn) * BN;

    const int wm = (warp & 1) * 64;           // warp M offset
    const int wn = (warp >> 1) * 64;          // warp N offset

    float acc[4][8][4];
#pragma unroll
    for (int mi = 0; mi < 4; mi++)
#pragma unroll
        for (int ni = 0; ni < 8; ni++)
#pragma unroll
            for (int e = 0; e < 4; e++) acc[mi][ni][e] = 0.0f;

    // ---- global -> shared: 16 x 16B cp.async per thread per k-tile ----
    auto issue = [&](int kt) {
        const uint32_t st = sb + (uint32_t)(kt % NSTAGE) * STAGE_BYTES;
        const int k0 = kt * BK;
#pragma unroll
        for (int i = 0; i < 16; i++) {
            int id = i * NTHREADS + tid;       // 0..2047
            int p = id >> 10;                  // 0 = A panel, 1 = B panel
            int r = (id >> 3) & 127;
            int c = id & 7;
            const __half* src = (p == 0)
                ? g_XH + (size_t)(m0 + r) * HID + k0 + c * 8
                : g_WH + (size_t)(n0 + r) * HID + k0 + c * 8;
            cpasync16(st + (uint32_t)p * A_PANEL + swz((uint32_t)r, (uint32_t)c), src);
        }
    };

    // prologue: 2 stages in flight
#pragma unroll
    for (int s = 0; s < NSTAGE - 1; s++) {
        issue(s);
        asm volatile("cp.async.commit_group;" ::: "memory");
    }

    // per-lane ldmatrix source coordinates
    const int arow = lane & 15;               // A: lanes 0-15 rows, 16-31 k+8
    const int ack = lane >> 4;
    const int brow = (lane & 7) + ((lane >> 4) << 3);  // B: 2 n8-tiles per x4
    const int bck = (lane >> 3) & 1;

    for (int kt = 0; kt < NKT; kt++) {
        asm volatile("cp.async.wait_group 1;" ::: "memory");
        __syncthreads();

        const uint32_t st = sb + (uint32_t)(kt % NSTAGE) * STAGE_BYTES;
        const uint32_t aH = st;
        const uint32_t bH = st + A_PANEL;

#pragma unroll
        for (int kh = 0; kh < 4; kh++) {       // 4 x k16 inside one barrier
            uint32_t ra[4][4], rb[4][4];
#pragma unroll
            for (int mi = 0; mi < 4; mi++)
                LDSM4(ra[mi], aH + swz((uint32_t)(wm + mi * 16 + arow),
                                       (uint32_t)(kh * 2 + ack)));
#pragma unroll
            for (int nj = 0; nj < 4; nj++)
                LDSM4(rb[nj], bH + swz((uint32_t)(wn + nj * 16 + brow),
                                       (uint32_t)(kh * 2 + bck)));
#pragma unroll
            for (int mi = 0; mi < 4; mi++)
#pragma unroll
                for (int ni = 0; ni < 8; ni++)
                    MMA16816(acc[mi][ni], ra[mi],
                             rb[ni >> 1][(ni & 1) * 2], rb[ni >> 1][(ni & 1) * 2 + 1]);
        }

        if (kt + NSTAGE - 1 < NKT) issue(kt + NSTAGE - 1);
        asm volatile("cp.async.commit_group;" ::: "memory");
    }

    // ---- epilogue: regs -> smem (stride 132) -> coalesced STG + bias ----
    __syncthreads();
    float* C = reinterpret_cast<float*>(smem);
    const int g = lane >> 2, tg = lane & 3;
#pragma unroll
    for (int mi = 0; mi < 4; mi++) {
#pragma unroll
        for (int ni = 0; ni < 8; ni++) {
            int row = wm + mi * 16 + g;
            int col = wn + ni * 8 + tg * 2;
            *reinterpret_cast<float2*>(&C[row * 132 + col]) =
                make_float2(acc[mi][ni][0], acc[mi][ni][1]);
            *reinterpret_cast<float2*>(&C[(row + 8) * 132 + col]) =
                make_float2(acc[mi][ni][2], acc[mi][ni][3]);
        }
    }
    __syncthreads();
#pragma unroll
    for (int i = 0; i < 32; i++) {
        int idx = tid + i * NTHREADS;          // 4096 float4 total
        int row = idx >> 5;                    // 32 float4 per row of 128 cols
        int col = (idx & 31) * 4;
        float4 b = *reinterpret_cast<const float4*>(bias + n0 + col);
        float4 v = *reinterpret_cast<const float4*>(&C[row * 132 + col]);
        v.x += b.x; v.y += b.y; v.z += b.z; v.w += b.w;
        *reinterpret_cast<float4*>(out + (size_t)(m0 + row) * HID + n0 + col) = v;
    }
}

// ---------------------------------------------------------------------------

extern "C" void kernel_launch(void* const* d_in, const int* in_sizes, int n_in,
                              void* d_out, int out_size) {
    const float* x    = (const float*)d_in[0];
    const float* w    = (const float*)d_in[1];
    const float* bias = (const float*)d_in[2];
    const int* sp     = (const int*)d_in[4];
    float* out = (float*)d_out;
    (void)in_sizes; (void)n_in; (void)out_size;

    cudaFuncSetAttribute(gemm_kernel, cudaFuncAttributeMaxDynamicSharedMemorySize,
                         SMEM_BYTES);

    prep_kernel<<<WBLK + XBLK, 256>>>(w, sp, x);
    gemm_kernel<<<(BATCH / BM) * (HID / BN), NTHREADS, SMEM_BYTES>>>(out, bias);
}